// round 11
// baseline (speedup 1.0000x reference)
#include <cuda_runtime.h>
#include <math.h>
#include <stdint.h>

#define N_TOK 2304
#define DIM   384
#define KD    32
#define NHEAD 8
#define DV    128
#define NHKD  256
#define DH    1024
#define RES   48
#define QSCALE 0.17677669529663687f   // 32^-0.5

// ---------------- scratch (no allocations allowed) ----------------
__device__ float g_qh [NHEAD * N_TOK * KD];   // head-major Q fp32
__device__ float g_khi[NHEAD * N_TOK * KD];   // head-major K hi (tf32)
__device__ float g_klo[NHEAD * N_TOK * KD];   // head-major K lo (tf32)
__device__ float g_vt [NHEAD * N_TOK * DV];   // head-major V (tf32)
__device__ float g_ohi[N_TOK * DH];           // attn out hi (tf32)
__device__ float g_olo[N_TOK * DH];           // attn out lo (tf32)

__device__ float g_xhi [N_TOK * DIM],  g_xlo [N_TOK * DIM];
__device__ float g_qwhi[NHKD * DIM],   g_qwlo[NHKD * DIM];
__device__ float g_kwhi[NHKD * DIM],   g_kwlo[NHKD * DIM];
__device__ float g_vwhi[DH * DIM],     g_vwlo[DH * DIM];
__device__ float g_pwhi[DIM * DH],     g_pwlo[DIM * DH];

// ======================================================================
// helpers
// ======================================================================
__device__ __forceinline__ uint32_t f2tf32(float x) {
    uint32_t r;
    asm("cvt.rna.tf32.f32 %0, %1;" : "=r"(r) : "f"(x));
    return r;
}

__device__ __forceinline__ void mma_tf32(float& d0, float& d1, float& d2, float& d3,
                                         uint32_t a0, uint32_t a1, uint32_t a2, uint32_t a3,
                                         uint32_t b0, uint32_t b1) {
    asm volatile(
        "mma.sync.aligned.m16n8k8.row.col.f32.tf32.tf32.f32 "
        "{%0,%1,%2,%3}, {%4,%5,%6,%7}, {%8,%9}, {%0,%1,%2,%3};\n"
        : "+f"(d0), "+f"(d1), "+f"(d2), "+f"(d3)
        : "r"(a0), "r"(a1), "r"(a2), "r"(a3), "r"(b0), "r"(b1));
}

__device__ __forceinline__ void cp_async16(uint32_t dst, const float* src) {
    asm volatile("cp.async.cg.shared.global [%0], [%1], 16;" :: "r"(dst), "l"(src));
}
__device__ __forceinline__ void cp_commit() {
    asm volatile("cp.async.commit_group;");
}

// ======================================================================
// split_prep: hi/lo tf32 split of x and the four weight matrices.
// ======================================================================
#define XN  (N_TOK * DIM)
#define QWN (NHKD * DIM)
#define VWN (DH * DIM)
#define PWN (DIM * DH)
#define PREP_TOT (XN + 2 * QWN + VWN + PWN)   // 1867776 = 7296*256

__global__ void split_prep(const float* __restrict__ x,  const float* __restrict__ qw,
                           const float* __restrict__ kw, const float* __restrict__ vw,
                           const float* __restrict__ pw) {
    int i = blockIdx.x * 256 + threadIdx.x;
    if (i >= PREP_TOT) return;
    const float* src; float* hi; float* lo; int off;
    if (i < XN)                      { src = x;  hi = g_xhi;  lo = g_xlo;  off = i; }
    else if (i < XN + QWN)           { src = qw; hi = g_qwhi; lo = g_qwlo; off = i - XN; }
    else if (i < XN + 2 * QWN)       { src = kw; hi = g_kwhi; lo = g_kwlo; off = i - XN - QWN; }
    else if (i < XN + 2 * QWN + VWN) { src = vw; hi = g_vwhi; lo = g_vwlo; off = i - XN - 2 * QWN; }
    else                             { src = pw; hi = g_pwhi; lo = g_pwlo; off = i - XN - 2 * QWN - VWN; }
    float v = src[off];
    uint32_t hb = f2tf32(v);
    hi[off] = __uint_as_float(hb);
    lo[off] = __uint_as_float(f2tf32(v - __uint_as_float(hb)));
}

// ======================================================================
// 3xTF32 GEMM mainloop: acc[8][4] += X[m0+64][K] @ W[n0+64][K]^T
// BM=64 BN=64 BK=32, 4 warps / 128 threads, double-buffered cp.async.
// smem: [b][ XH 2304 | XL 2304 | WH 2304 | WL 2304 ]   (stride 36)
// ======================================================================
#define GB_XH 0
#define GB_XL 2304
#define GB_WH 4608
#define GB_WL 6912
#define GB_SZ 9216
#define GEMM_SMEM_FLOATS (2 * GB_SZ)          // 18432 floats = 73728 B

template<int KDIM>
__device__ __forceinline__ void gemm3x_main(
    const float* __restrict__ Xhi, const float* __restrict__ Xlo,
    const float* __restrict__ Whi, const float* __restrict__ Wlo,
    int m0, int n0, float* smp, uint32_t smb, float acc[8][4])
{
    const int t = threadIdx.x, w = t >> 5, lane = t & 31;
    const int gid = lane >> 2, tig = lane & 3;

    auto issue = [&](int k0, int b) {
        #pragma unroll
        for (int i = 0; i < 4; i++) {
            int idx = t + i * 128;
            int r = idx >> 3, f4 = idx & 7;
            cp_async16(smb + (b * GB_SZ + GB_XH + r * 36 + f4 * 4) * 4,
                       Xhi + (m0 + r) * KDIM + k0 + f4 * 4);
            cp_async16(smb + (b * GB_SZ + GB_XL + r * 36 + f4 * 4) * 4,
                       Xlo + (m0 + r) * KDIM + k0 + f4 * 4);
            cp_async16(smb + (b * GB_SZ + GB_WH + r * 36 + f4 * 4) * 4,
                       Whi + (n0 + r) * KDIM + k0 + f4 * 4);
            cp_async16(smb + (b * GB_SZ + GB_WL + r * 36 + f4 * 4) * 4,
                       Wlo + (n0 + r) * KDIM + k0 + f4 * 4);
        }
    };

    issue(0, 0);
    cp_commit();

    const int NT = KDIM / 32;
    for (int kt = 0; kt < NT; kt++) {
        const int b = kt & 1;
        if (kt + 1 < NT) {
            issue((kt + 1) * 32, b ^ 1);
            cp_commit();
            asm volatile("cp.async.wait_group 1;");
        } else {
            asm volatile("cp.async.wait_group 0;");
        }
        __syncthreads();

        float* XH = smp + b * GB_SZ + GB_XH;
        float* XL = smp + b * GB_SZ + GB_XL;
        float* WH = smp + b * GB_SZ + GB_WH;
        float* WL = smp + b * GB_SZ + GB_WL;

        #pragma unroll
        for (int ks = 0; ks < 4; ks++) {
            const int row = w * 16 + gid;
            const int kc = ks * 8 + tig;
            uint32_t ah0 = __float_as_uint(XH[row * 36 + kc]);
            uint32_t ah1 = __float_as_uint(XH[(row + 8) * 36 + kc]);
            uint32_t ah2 = __float_as_uint(XH[row * 36 + kc + 4]);
            uint32_t ah3 = __float_as_uint(XH[(row + 8) * 36 + kc + 4]);
            uint32_t al0 = __float_as_uint(XL[row * 36 + kc]);
            uint32_t al1 = __float_as_uint(XL[(row + 8) * 36 + kc]);
            uint32_t al2 = __float_as_uint(XL[row * 36 + kc + 4]);
            uint32_t al3 = __float_as_uint(XL[(row + 8) * 36 + kc + 4]);
            #pragma unroll
            for (int nt = 0; nt < 8; nt++) {
                const int nr = nt * 8 + gid;
                uint32_t bh0 = __float_as_uint(WH[nr * 36 + kc]);
                uint32_t bh1 = __float_as_uint(WH[nr * 36 + kc + 4]);
                uint32_t bl0 = __float_as_uint(WL[nr * 36 + kc]);
                uint32_t bl1 = __float_as_uint(WL[nr * 36 + kc + 4]);
                mma_tf32(acc[nt][0], acc[nt][1], acc[nt][2], acc[nt][3],
                         ah0, ah1, ah2, ah3, bh0, bh1);
                mma_tf32(acc[nt][0], acc[nt][1], acc[nt][2], acc[nt][3],
                         al0, al1, al2, al3, bh0, bh1);
                mma_tf32(acc[nt][0], acc[nt][1], acc[nt][2], acc[nt][3],
                         ah0, ah1, ah2, ah3, bl0, bl1);
            }
        }
        __syncthreads();
    }
}

// ======================================================================
// Fused QKV projection via 3xTF32 mma. grid (36, 24), 128 threads.
// ======================================================================
__global__ __launch_bounds__(128)
void qkv_mma(const float* __restrict__ qbias, const float* __restrict__ kbias,
             const float* __restrict__ vbias) {
    extern __shared__ float smp[];
    const uint32_t smb = (uint32_t)__cvta_generic_to_shared(smp);
    const int t = threadIdx.x, w = t >> 5, lane = t & 31;
    const int gid = lane >> 2, tig = lane & 3;
    const int m0 = blockIdx.x * 64;
    const int y = blockIdx.y;

    int seg, nbase;
    const float *Whi, *Wlo, *B;
    if (y < 4)      { seg = 0; Whi = g_qwhi; Wlo = g_qwlo; B = qbias; nbase = y * 64; }
    else if (y < 8) { seg = 1; Whi = g_kwhi; Wlo = g_kwlo; B = kbias; nbase = (y - 4) * 64; }
    else            { seg = 2; Whi = g_vwhi; Wlo = g_vwlo; B = vbias; nbase = (y - 8) * 64; }

    float acc[8][4];
    #pragma unroll
    for (int nt = 0; nt < 8; nt++)
        #pragma unroll
        for (int i = 0; i < 4; i++) acc[nt][i] = 0.0f;

    gemm3x_main<DIM>(g_xhi, g_xlo, Whi, Wlo, m0, nbase, smp, smb, acc);

    const int mA = m0 + w * 16 + gid;
    const int mB = mA + 8;
    #pragma unroll
    for (int nt = 0; nt < 8; nt++) {
        const int n = nbase + nt * 8 + 2 * tig;
        const float bv0 = B[n], bv1 = B[n + 1];
        float v00 = acc[nt][0] + bv0, v01 = acc[nt][1] + bv1;
        float v10 = acc[nt][2] + bv0, v11 = acc[nt][3] + bv1;
        if (seg == 0) {
            int hh = n >> 5, c = n & 31;
            float* d0 = &g_qh[(hh * N_TOK + mA) * KD + c];
            float* d1 = &g_qh[(hh * N_TOK + mB) * KD + c];
            d0[0] = v00; d0[1] = v01;
            d1[0] = v10; d1[1] = v11;
        } else if (seg == 1) {
            int hh = n >> 5, c = n & 31;
            int iA = (hh * N_TOK + mA) * KD + c;
            int iB = (hh * N_TOK + mB) * KD + c;
            uint32_t h00 = f2tf32(v00), h01 = f2tf32(v01);
            uint32_t h10 = f2tf32(v10), h11 = f2tf32(v11);
            g_khi[iA] = __uint_as_float(h00); g_khi[iA + 1] = __uint_as_float(h01);
            g_khi[iB] = __uint_as_float(h10); g_khi[iB + 1] = __uint_as_float(h11);
            g_klo[iA]     = __uint_as_float(f2tf32(v00 - __uint_as_float(h00)));
            g_klo[iA + 1] = __uint_as_float(f2tf32(v01 - __uint_as_float(h01)));
            g_klo[iB]     = __uint_as_float(f2tf32(v10 - __uint_as_float(h10)));
            g_klo[iB + 1] = __uint_as_float(f2tf32(v11 - __uint_as_float(h11)));
        } else {
            int hh = n >> 7, c = n & 127;
            int iA = (hh * N_TOK + mA) * DV + c;
            int iB = (hh * N_TOK + mB) * DV + c;
            g_vt[iA]     = __uint_as_float(f2tf32(v00));
            g_vt[iA + 1] = __uint_as_float(f2tf32(v01));
            g_vt[iB]     = __uint_as_float(f2tf32(v10));
            g_vt[iB + 1] = __uint_as_float(f2tf32(v11));
        }
    }
}

// ======================================================================
// Output projection via 3xTF32 mma. grid (36, 6), 128 threads.
// ======================================================================
__global__ __launch_bounds__(128)
void proj_mma(const float* __restrict__ pbias, float* __restrict__ out) {
    extern __shared__ float smp[];
    const uint32_t smb = (uint32_t)__cvta_generic_to_shared(smp);
    const int t = threadIdx.x, w = t >> 5, lane = t & 31;
    const int gid = lane >> 2, tig = lane & 3;
    const int m0 = blockIdx.x * 64;
    const int n0 = blockIdx.y * 64;

    float acc[8][4];
    #pragma unroll
    for (int nt = 0; nt < 8; nt++)
        #pragma unroll
        for (int i = 0; i < 4; i++) acc[nt][i] = 0.0f;

    gemm3x_main<DH>(g_ohi, g_olo, g_pwhi, g_pwlo, m0, n0, smp, smb, acc);

    const int mA = m0 + w * 16 + gid;
    const int mB = mA + 8;
    #pragma unroll
    for (int nt = 0; nt < 8; nt++) {
        const int n = n0 + nt * 8 + 2 * tig;
        const float bv0 = pbias[n], bv1 = pbias[n + 1];
        float2 r0, r1;
        r0.x = acc[nt][0] + bv0; r0.y = acc[nt][1] + bv1;
        r1.x = acc[nt][2] + bv0; r1.y = acc[nt][3] + bv1;
        *(float2*)&out[mA * DIM + n] = r0;
        *(float2*)&out[mB * DIM + n] = r1;
    }
}

// ======================================================================
// Flash attention, tf32 mma.  BM=64, 128 threads (4 warps), 2 CTAs/SM.
// Double-buffered K, single V with split wait_groups:
//   K(t+1) issued after QK^T (overlaps softmax+PV)
//   V(t) waited only before P*V (its load overlaps QK^T+softmax)
// ======================================================================
#define BM 64
#define BN 64
#define NTILE (N_TOK / BN)
#define KSTR 36
#define VSTR 136
#define PSTR 68

#define OF_K(b)  ((b) * 4608)            // Khi at +0, Klo at +2304
#define OF_V     9216                    // 64*136 = 8704
#define OF_PS    17920                   // 64*68  = 4352
#define OF_BIA   22272                   // 2304
#define SM_TOT   24576                   // floats = 98304 bytes

__global__ __launch_bounds__(128)
void attn_mma(const float* __restrict__ Qg,
              const float* __restrict__ Khig,
              const float* __restrict__ Klog,
              const float* __restrict__ Vg,
              const float* __restrict__ biases) {   // [8, 2304]
    extern __shared__ float sm[];
    const uint32_t smb = (uint32_t)__cvta_generic_to_shared(sm);
    float* Ps = sm + OF_PS;
    float* bias_sm = sm + OF_BIA;
    float* Vs = sm + OF_V;

    const int t    = threadIdx.x;
    const int w    = t >> 5;             // 0..3
    const int lane = t & 31;
    const int gid  = lane >> 2;
    const int tig  = lane & 3;
    const int qb   = blockIdx.x * BM;
    const int h    = blockIdx.y;

    const float* Kh_base = Khig + (h * N_TOK) * KD;
    const float* Kl_base = Klog + (h * N_TOK) * KD;
    const float* V_base  = Vg   + (h * N_TOK) * DV;

    const int row0 = qb + 16 * w + gid;
    const int row1 = row0 + 8;
    const int qy0 = row0 / RES, qx0 = row0 % RES;
    const int qy1 = row1 / RES, qx1 = row1 % RES;

    for (int i = t; i < N_TOK; i += 128)
        bias_sm[i] = biases[h * N_TOK + i];

    // loop-invariant Q fragments
    uint32_t qhi[4][4], qlo[4][4];
    {
        const float* Qrow0 = Qg + (h * N_TOK + row0) * KD;
        const float* Qrow1 = Qg + (h * N_TOK + row1) * KD;
        #pragma unroll
        for (int ks = 0; ks < 4; ks++) {
            float x0 = Qrow0[ks * 8 + tig];
            float x1 = Qrow1[ks * 8 + tig];
            float x2 = Qrow0[ks * 8 + tig + 4];
            float x3 = Qrow1[ks * 8 + tig + 4];
            uint32_t h0 = f2tf32(x0), h1 = f2tf32(x1), h2 = f2tf32(x2), h3 = f2tf32(x3);
            qhi[ks][0] = h0; qhi[ks][1] = h1; qhi[ks][2] = h2; qhi[ks][3] = h3;
            qlo[ks][0] = f2tf32(x0 - __uint_as_float(h0));
            qlo[ks][1] = f2tf32(x1 - __uint_as_float(h1));
            qlo[ks][2] = f2tf32(x2 - __uint_as_float(h2));
            qlo[ks][3] = f2tf32(x3 - __uint_as_float(h3));
        }
    }

    auto issue_K = [&](int kt, int b) {
        const int kb = kt * BN;
        const float* kh = Kh_base + kb * KD;
        const float* kl = Kl_base + kb * KD;
        #pragma unroll
        for (int i = 0; i < 4; i++) {
            int idx = t + i * 128;
            int r = idx >> 3, f4 = idx & 7;
            cp_async16(smb + (OF_K(b) + r * KSTR + f4 * 4) * 4, kh + r * KD + f4 * 4);
            cp_async16(smb + (OF_K(b) + 2304 + r * KSTR + f4 * 4) * 4, kl + r * KD + f4 * 4);
        }
    };
    auto issue_V = [&](int kt) {
        const int kb = kt * BN;
        const float* vv = V_base + kb * DV;
        #pragma unroll
        for (int i = 0; i < 16; i++) {
            int idx = t + i * 128;
            int r = idx >> 5, c4 = idx & 31;
            cp_async16(smb + (OF_V + r * VSTR + c4 * 4) * 4, vv + r * DV + c4 * 4);
        }
    };

    float m_r0 = -1e30f, m_r1 = -1e30f;
    float l_r0 = 0.0f,   l_r1 = 0.0f;
    float o[16][4];
    #pragma unroll
    for (int nt = 0; nt < 16; nt++)
        #pragma unroll
        for (int i = 0; i < 4; i++) o[nt][i] = 0.0f;

    // prologue: pending groups = { K0, V0 }
    issue_K(0, 0); cp_commit();
    issue_V(0);    cp_commit();

    for (int kt = 0; kt < NTILE; kt++) {
        const int b  = kt & 1;
        const int kb = kt * BN;
        float* Khi = sm + OF_K(b);
        float* Klo = Khi + 2304;

        // wait K(kt) (leave V(kt) in flight), barrier for cross-thread visibility
        asm volatile("cp.async.wait_group 1;");
        __syncthreads();

        // ---- S = Q K^T (3x tf32) ----
        float sfr[8][4];
        #pragma unroll
        for (int nt = 0; nt < 8; nt++)
            #pragma unroll
            for (int i = 0; i < 4; i++) sfr[nt][i] = 0.0f;

        #pragma unroll
        for (int ks = 0; ks < 4; ks++) {
            #pragma unroll
            for (int nt = 0; nt < 8; nt++) {
                int nrow = nt * 8 + gid;
                uint32_t bh0 = __float_as_uint(Khi[nrow * KSTR + ks * 8 + tig]);
                uint32_t bh1 = __float_as_uint(Khi[nrow * KSTR + ks * 8 + tig + 4]);
                uint32_t bl0 = __float_as_uint(Klo[nrow * KSTR + ks * 8 + tig]);
                uint32_t bl1 = __float_as_uint(Klo[nrow * KSTR + ks * 8 + tig + 4]);
                mma_tf32(sfr[nt][0], sfr[nt][1], sfr[nt][2], sfr[nt][3],
                         qhi[ks][0], qhi[ks][1], qhi[ks][2], qhi[ks][3], bh0, bh1);
                mma_tf32(sfr[nt][0], sfr[nt][1], sfr[nt][2], sfr[nt][3],
                         qlo[ks][0], qlo[ks][1], qlo[ks][2], qlo[ks][3], bh0, bh1);
                mma_tf32(sfr[nt][0], sfr[nt][1], sfr[nt][2], sfr[nt][3],
                         qhi[ks][0], qhi[ks][1], qhi[ks][2], qhi[ks][3], bl0, bl1);
            }
        }

        // prefetch K(kt+1) into the other K buffer (free since kt-1, fenced by barriers)
        if (kt + 1 < NTILE) { issue_K(kt + 1, b ^ 1); cp_commit(); }

        // ---- scale + bias, row max ----
        float mx0 = -1e30f, mx1 = -1e30f;
        #pragma unroll
        for (int nt = 0; nt < 8; nt++) {
            int ck0 = kb + nt * 8 + 2 * tig;
            int ck1 = ck0 + 1;
            int ky0 = ck0 / RES, kx0 = ck0 % RES;
            int ky1 = ck1 / RES, kx1 = ck1 % RES;
            float b00 = bias_sm[abs(qy0 - ky0) * RES + abs(qx0 - kx0)];
            float b01 = bias_sm[abs(qy0 - ky1) * RES + abs(qx0 - kx1)];
            float b10 = bias_sm[abs(qy1 - ky0) * RES + abs(qx1 - kx0)];
            float b11 = bias_sm[abs(qy1 - ky1) * RES + abs(qx1 - kx1)];
            sfr[nt][0] = sfr[nt][0] * QSCALE + b00;
            sfr[nt][1] = sfr[nt][1] * QSCALE + b01;
            sfr[nt][2] = sfr[nt][2] * QSCALE + b10;
            sfr[nt][3] = sfr[nt][3] * QSCALE + b11;
            mx0 = fmaxf(mx0, fmaxf(sfr[nt][0], sfr[nt][1]));
            mx1 = fmaxf(mx1, fmaxf(sfr[nt][2], sfr[nt][3]));
        }
        mx0 = fmaxf(mx0, __shfl_xor_sync(0xffffffffu, mx0, 1));
        mx0 = fmaxf(mx0, __shfl_xor_sync(0xffffffffu, mx0, 2));
        mx1 = fmaxf(mx1, __shfl_xor_sync(0xffffffffu, mx1, 1));
        mx1 = fmaxf(mx1, __shfl_xor_sync(0xffffffffu, mx1, 2));

        float mn0 = fmaxf(m_r0, mx0);
        float mn1 = fmaxf(m_r1, mx1);
        float al0 = __expf(m_r0 - mn0);
        float al1 = __expf(m_r1 - mn1);
        m_r0 = mn0; m_r1 = mn1;

        // ---- P = exp(S - m), tf32 into smem, row sums ----
        float sum0 = 0.0f, sum1 = 0.0f;
        const int prow0 = (16 * w + gid) * PSTR;
        const int prow1 = (16 * w + gid + 8) * PSTR;
        #pragma unroll
        for (int nt = 0; nt < 8; nt++) {
            float p0 = __expf(sfr[nt][0] - mn0);
            float p1 = __expf(sfr[nt][1] - mn0);
            float p2 = __expf(sfr[nt][2] - mn1);
            float p3 = __expf(sfr[nt][3] - mn1);
            sum0 += p0 + p1;
            sum1 += p2 + p3;
            float2 w0, w1;
            w0.x = __uint_as_float(f2tf32(p0));
            w0.y = __uint_as_float(f2tf32(p1));
            w1.x = __uint_as_float(f2tf32(p2));
            w1.y = __uint_as_float(f2tf32(p3));
            *(float2*)&Ps[prow0 + nt * 8 + 2 * tig] = w0;
            *(float2*)&Ps[prow1 + nt * 8 + 2 * tig] = w1;
        }
        sum0 += __shfl_xor_sync(0xffffffffu, sum0, 1);
        sum0 += __shfl_xor_sync(0xffffffffu, sum0, 2);
        sum1 += __shfl_xor_sync(0xffffffffu, sum1, 1);
        sum1 += __shfl_xor_sync(0xffffffffu, sum1, 2);
        l_r0 = l_r0 * al0 + sum0;
        l_r1 = l_r1 * al1 + sum1;

        // rescale O accumulators (register-only, before the V wait)
        #pragma unroll
        for (int nt = 0; nt < 16; nt++) {
            o[nt][0] *= al0; o[nt][1] *= al0;
            o[nt][2] *= al1; o[nt][3] *= al1;
        }

        // wait V(kt): leave only the just-issued K(kt+1) in flight.
        // Barrier also publishes Ps to all warps.
        if (kt + 1 < NTILE) {
            asm volatile("cp.async.wait_group 1;");
        } else {
            asm volatile("cp.async.wait_group 0;");
        }
        __syncthreads();

        // ---- O += P * V (1x tf32) ----
        #pragma unroll
        for (int ks = 0; ks < 8; ks++) {
            uint32_t pa0 = __float_as_uint(Ps[prow0 + ks * 8 + tig]);
            uint32_t pa1 = __float_as_uint(Ps[prow1 + ks * 8 + tig]);
            uint32_t pa2 = __float_as_uint(Ps[prow0 + ks * 8 + tig + 4]);
            uint32_t pa3 = __float_as_uint(Ps[prow1 + ks * 8 + tig + 4]);
            #pragma unroll
            for (int nt = 0; nt < 16; nt++) {
                uint32_t vb0 = __float_as_uint(Vs[(ks * 8 + tig) * VSTR + nt * 8 + gid]);
                uint32_t vb1 = __float_as_uint(Vs[(ks * 8 + tig + 4) * VSTR + nt * 8 + gid]);
                mma_tf32(o[nt][0], o[nt][1], o[nt][2], o[nt][3],
                         pa0, pa1, pa2, pa3, vb0, vb1);
            }
        }
        __syncthreads();   // all warps done reading V (and Ps) before refill

        if (kt + 1 < NTILE) { issue_V(kt + 1); cp_commit(); }
    }

    // ---- epilogue: normalize, split hi/lo for proj ----
    float inv0 = 1.0f / l_r0;
    float inv1 = 1.0f / l_r1;
    #pragma unroll
    for (int nt = 0; nt < 16; nt++) {
        float v00 = o[nt][0] * inv0, v01 = o[nt][1] * inv0;
        float v10 = o[nt][2] * inv1, v11 = o[nt][3] * inv1;
        uint32_t h00 = f2tf32(v00), h01 = f2tf32(v01);
        uint32_t h10 = f2tf32(v10), h11 = f2tf32(v11);
        float2 hi0, hi1, lo0, lo1;
        hi0.x = __uint_as_float(h00); hi0.y = __uint_as_float(h01);
        hi1.x = __uint_as_float(h10); hi1.y = __uint_as_float(h11);
        lo0.x = __uint_as_float(f2tf32(v00 - __uint_as_float(h00)));
        lo0.y = __uint_as_float(f2tf32(v01 - __uint_as_float(h01)));
        lo1.x = __uint_as_float(f2tf32(v10 - __uint_as_float(h10)));
        lo1.y = __uint_as_float(f2tf32(v11 - __uint_as_float(h11)));
        long iA = (long)row0 * DH + h * DV + nt * 8 + 2 * tig;
        long iB = (long)row1 * DH + h * DV + nt * 8 + 2 * tig;
        *(float2*)&g_ohi[iA] = hi0;
        *(float2*)&g_ohi[iB] = hi1;
        *(float2*)&g_olo[iA] = lo0;
        *(float2*)&g_olo[iB] = lo1;
    }
}

// ======================================================================
extern "C" void kernel_launch(void* const* d_in, const int* in_sizes, int n_in,
                              void* d_out, int out_size) {
    const float* x       = (const float*)d_in[0];
    const float* q_w     = (const float*)d_in[1];
    const float* q_b     = (const float*)d_in[2];
    const float* k_w     = (const float*)d_in[3];
    const float* k_b     = (const float*)d_in[4];
    const float* v_w     = (const float*)d_in[5];
    const float* v_b     = (const float*)d_in[6];
    const float* proj_w  = (const float*)d_in[7];
    const float* proj_b  = (const float*)d_in[8];
    const float* abias   = (const float*)d_in[9];
    float* out           = (float*)d_out;

    float *pq, *pkh, *pkl, *pv;
    cudaGetSymbolAddress((void**)&pq,  g_qh);
    cudaGetSymbolAddress((void**)&pkh, g_khi);
    cudaGetSymbolAddress((void**)&pkl, g_klo);
    cudaGetSymbolAddress((void**)&pv,  g_vt);

    // 1. hi/lo split of x + weights
    split_prep<<<PREP_TOT / 256, 256>>>(x, q_w, k_w, v_w, proj_w);

    // 2. fused QKV projection (3xTF32 mma), 2 CTAs/SM
    const int gemm_smem = GEMM_SMEM_FLOATS * (int)sizeof(float);
    cudaFuncSetAttribute(qkv_mma, cudaFuncAttributeMaxDynamicSharedMemorySize, gemm_smem);
    qkv_mma<<<dim3(N_TOK / 64, 24), 128, gemm_smem>>>(q_b, k_b, v_b);

    // 3. fused attention (tf32 mma flash, split-wait cp.async), 2 CTAs/SM
    const int attn_smem = SM_TOT * (int)sizeof(float);
    cudaFuncSetAttribute(attn_mma, cudaFuncAttributeMaxDynamicSharedMemorySize, attn_smem);
    attn_mma<<<dim3(N_TOK / BM, NHEAD), 128, attn_smem>>>(pq, pkh, pkl, pv, abias);

    // 4. output projection (3xTF32 mma) -> d_out, 2 CTAs/SM
    cudaFuncSetAttribute(proj_mma, cudaFuncAttributeMaxDynamicSharedMemorySize, gemm_smem);
    proj_mma<<<dim3(N_TOK / 64, DIM / 64), 128, gemm_smem>>>(proj_b, out);
}

// round 12
// speedup vs baseline: 1.1444x; 1.1444x over previous
#include <cuda_runtime.h>
#include <math.h>
#include <stdint.h>

#define N_TOK 2304
#define DIM   384
#define KD    32
#define NHEAD 8
#define DV    128
#define NHKD  256
#define DH    1024
#define RES   48
#define QSCALE 0.17677669529663687f   // 32^-0.5

// ---------------- scratch (no allocations allowed) ----------------
__device__ float g_qh [NHEAD * N_TOK * KD];   // head-major Q fp32
__device__ float g_khi[NHEAD * N_TOK * KD];   // head-major K hi (tf32)
__device__ float g_klo[NHEAD * N_TOK * KD];   // head-major K lo (tf32)
__device__ float g_vt [NHEAD * N_TOK * DV];   // head-major V (tf32)
__device__ float g_ohi[N_TOK * DH];           // attn out hi (tf32)
__device__ float g_olo[N_TOK * DH];           // attn out lo (tf32)

__device__ float g_xhi [N_TOK * DIM],  g_xlo [N_TOK * DIM];
__device__ float g_qwhi[NHKD * DIM],   g_qwlo[NHKD * DIM];
__device__ float g_kwhi[NHKD * DIM],   g_kwlo[NHKD * DIM];
__device__ float g_vwhi[DH * DIM],     g_vwlo[DH * DIM];
__device__ float g_pwhi[DIM * DH],     g_pwlo[DIM * DH];

#define PROJ_SPLIT 4
__device__ float g_pp[PROJ_SPLIT * N_TOK * DIM];   // proj partial sums

// ======================================================================
// helpers
// ======================================================================
__device__ __forceinline__ uint32_t f2tf32(float x) {
    uint32_t r;
    asm("cvt.rna.tf32.f32 %0, %1;" : "=r"(r) : "f"(x));
    return r;
}

__device__ __forceinline__ void mma_tf32(float& d0, float& d1, float& d2, float& d3,
                                         uint32_t a0, uint32_t a1, uint32_t a2, uint32_t a3,
                                         uint32_t b0, uint32_t b1) {
    asm volatile(
        "mma.sync.aligned.m16n8k8.row.col.f32.tf32.tf32.f32 "
        "{%0,%1,%2,%3}, {%4,%5,%6,%7}, {%8,%9}, {%0,%1,%2,%3};\n"
        : "+f"(d0), "+f"(d1), "+f"(d2), "+f"(d3)
        : "r"(a0), "r"(a1), "r"(a2), "r"(a3), "r"(b0), "r"(b1));
}

__device__ __forceinline__ void cp_async16(uint32_t dst, const float* src) {
    asm volatile("cp.async.cg.shared.global [%0], [%1], 16;" :: "r"(dst), "l"(src));
}
__device__ __forceinline__ void cp_commit() {
    asm volatile("cp.async.commit_group;");
}

// ======================================================================
// split_prep: hi/lo tf32 split of x and the four weight matrices.
// ======================================================================
#define XN  (N_TOK * DIM)
#define QWN (NHKD * DIM)
#define VWN (DH * DIM)
#define PWN (DIM * DH)
#define PREP_TOT (XN + 2 * QWN + VWN + PWN)   // 1867776 = 7296*256

__global__ void split_prep(const float* __restrict__ x,  const float* __restrict__ qw,
                           const float* __restrict__ kw, const float* __restrict__ vw,
                           const float* __restrict__ pw) {
    int i = blockIdx.x * 256 + threadIdx.x;
    if (i >= PREP_TOT) return;
    const float* src; float* hi; float* lo; int off;
    if (i < XN)                      { src = x;  hi = g_xhi;  lo = g_xlo;  off = i; }
    else if (i < XN + QWN)           { src = qw; hi = g_qwhi; lo = g_qwlo; off = i - XN; }
    else if (i < XN + 2 * QWN)       { src = kw; hi = g_kwhi; lo = g_kwlo; off = i - XN - QWN; }
    else if (i < XN + 2 * QWN + VWN) { src = vw; hi = g_vwhi; lo = g_vwlo; off = i - XN - 2 * QWN; }
    else                             { src = pw; hi = g_pwhi; lo = g_pwlo; off = i - XN - 2 * QWN - VWN; }
    float v = src[off];
    uint32_t hb = f2tf32(v);
    hi[off] = __uint_as_float(hb);
    lo[off] = __uint_as_float(f2tf32(v - __uint_as_float(hb)));
}

// ======================================================================
// 3xTF32 GEMM mainloop: acc[8][4] += X[m0+128][kb..kb+KLEN] @ W[n0+64][..]^T
// BM=128 BN=64 BK=32, 8 warps / 256 threads, double-buffered cp.async.
// KSTRIDE = row stride of X/W; KLEN = length of K range processed.
// ======================================================================
#define GB_XH 0
#define GB_XL 4608
#define GB_WH 9216
#define GB_WL 11520
#define GB_SZ 13824
#define GEMM_SMEM_FLOATS (2 * GB_SZ)          // 27648 floats = 110592 B

template<int KSTRIDE, int KLEN>
__device__ __forceinline__ void gemm3x_main(
    const float* __restrict__ Xhi, const float* __restrict__ Xlo,
    const float* __restrict__ Whi, const float* __restrict__ Wlo,
    int m0, int n0, int kbase, float* smp, uint32_t smb, float acc[8][4])
{
    const int t = threadIdx.x, w = t >> 5, lane = t & 31;
    const int gid = lane >> 2, tig = lane & 3;

    auto issue = [&](int k0, int b) {
        #pragma unroll
        for (int i = 0; i < 4; i++) {
            int idx = t + i * 256;
            int r = idx >> 3, f4 = idx & 7;
            cp_async16(smb + (b * GB_SZ + GB_XH + r * 36 + f4 * 4) * 4,
                       Xhi + (m0 + r) * KSTRIDE + k0 + f4 * 4);
            cp_async16(smb + (b * GB_SZ + GB_XL + r * 36 + f4 * 4) * 4,
                       Xlo + (m0 + r) * KSTRIDE + k0 + f4 * 4);
        }
        #pragma unroll
        for (int i = 0; i < 2; i++) {
            int idx = t + i * 256;
            int r = idx >> 3, f4 = idx & 7;
            cp_async16(smb + (b * GB_SZ + GB_WH + r * 36 + f4 * 4) * 4,
                       Whi + (n0 + r) * KSTRIDE + k0 + f4 * 4);
            cp_async16(smb + (b * GB_SZ + GB_WL + r * 36 + f4 * 4) * 4,
                       Wlo + (n0 + r) * KSTRIDE + k0 + f4 * 4);
        }
    };

    issue(kbase, 0);
    cp_commit();

    const int NT = KLEN / 32;
    for (int kt = 0; kt < NT; kt++) {
        const int b = kt & 1;
        if (kt + 1 < NT) {
            issue(kbase + (kt + 1) * 32, b ^ 1);
            cp_commit();
            asm volatile("cp.async.wait_group 1;");
        } else {
            asm volatile("cp.async.wait_group 0;");
        }
        __syncthreads();

        float* XH = smp + b * GB_SZ + GB_XH;
        float* XL = smp + b * GB_SZ + GB_XL;
        float* WH = smp + b * GB_SZ + GB_WH;
        float* WL = smp + b * GB_SZ + GB_WL;

        #pragma unroll
        for (int ks = 0; ks < 4; ks++) {
            const int row = w * 16 + gid;
            const int kc = ks * 8 + tig;
            uint32_t ah0 = __float_as_uint(XH[row * 36 + kc]);
            uint32_t ah1 = __float_as_uint(XH[(row + 8) * 36 + kc]);
            uint32_t ah2 = __float_as_uint(XH[row * 36 + kc + 4]);
            uint32_t ah3 = __float_as_uint(XH[(row + 8) * 36 + kc + 4]);
            uint32_t al0 = __float_as_uint(XL[row * 36 + kc]);
            uint32_t al1 = __float_as_uint(XL[(row + 8) * 36 + kc]);
            uint32_t al2 = __float_as_uint(XL[row * 36 + kc + 4]);
            uint32_t al3 = __float_as_uint(XL[(row + 8) * 36 + kc + 4]);
            #pragma unroll
            for (int nt = 0; nt < 8; nt++) {
                const int nr = nt * 8 + gid;
                uint32_t bh0 = __float_as_uint(WH[nr * 36 + kc]);
                uint32_t bh1 = __float_as_uint(WH[nr * 36 + kc + 4]);
                uint32_t bl0 = __float_as_uint(WL[nr * 36 + kc]);
                uint32_t bl1 = __float_as_uint(WL[nr * 36 + kc + 4]);
                mma_tf32(acc[nt][0], acc[nt][1], acc[nt][2], acc[nt][3],
                         ah0, ah1, ah2, ah3, bh0, bh1);
                mma_tf32(acc[nt][0], acc[nt][1], acc[nt][2], acc[nt][3],
                         al0, al1, al2, al3, bh0, bh1);
                mma_tf32(acc[nt][0], acc[nt][1], acc[nt][2], acc[nt][3],
                         ah0, ah1, ah2, ah3, bl0, bl1);
            }
        }
        __syncthreads();
    }
}

// ======================================================================
// Fused QKV projection via 3xTF32 mma. grid (18, 24), 256 threads.
// ======================================================================
__global__ __launch_bounds__(256, 1)
void qkv_mma(const float* __restrict__ qbias, const float* __restrict__ kbias,
             const float* __restrict__ vbias) {
    extern __shared__ float smp[];
    const uint32_t smb = (uint32_t)__cvta_generic_to_shared(smp);
    const int t = threadIdx.x, w = t >> 5, lane = t & 31;
    const int gid = lane >> 2, tig = lane & 3;
    const int m0 = blockIdx.x * 128;
    const int y = blockIdx.y;

    int seg, nbase;
    const float *Whi, *Wlo, *B;
    if (y < 4)      { seg = 0; Whi = g_qwhi; Wlo = g_qwlo; B = qbias; nbase = y * 64; }
    else if (y < 8) { seg = 1; Whi = g_kwhi; Wlo = g_kwlo; B = kbias; nbase = (y - 4) * 64; }
    else            { seg = 2; Whi = g_vwhi; Wlo = g_vwlo; B = vbias; nbase = (y - 8) * 64; }

    float acc[8][4];
    #pragma unroll
    for (int nt = 0; nt < 8; nt++)
        #pragma unroll
        for (int i = 0; i < 4; i++) acc[nt][i] = 0.0f;

    gemm3x_main<DIM, DIM>(g_xhi, g_xlo, Whi, Wlo, m0, nbase, 0, smp, smb, acc);

    const int mA = m0 + w * 16 + gid;
    const int mB = mA + 8;
    #pragma unroll
    for (int nt = 0; nt < 8; nt++) {
        const int n = nbase + nt * 8 + 2 * tig;
        const float bv0 = B[n], bv1 = B[n + 1];
        float v00 = acc[nt][0] + bv0, v01 = acc[nt][1] + bv1;
        float v10 = acc[nt][2] + bv0, v11 = acc[nt][3] + bv1;
        if (seg == 0) {
            int hh = n >> 5, c = n & 31;
            float* d0 = &g_qh[(hh * N_TOK + mA) * KD + c];
            float* d1 = &g_qh[(hh * N_TOK + mB) * KD + c];
            d0[0] = v00; d0[1] = v01;
            d1[0] = v10; d1[1] = v11;
        } else if (seg == 1) {
            int hh = n >> 5, c = n & 31;
            int iA = (hh * N_TOK + mA) * KD + c;
            int iB = (hh * N_TOK + mB) * KD + c;
            uint32_t h00 = f2tf32(v00), h01 = f2tf32(v01);
            uint32_t h10 = f2tf32(v10), h11 = f2tf32(v11);
            g_khi[iA] = __uint_as_float(h00); g_khi[iA + 1] = __uint_as_float(h01);
            g_khi[iB] = __uint_as_float(h10); g_khi[iB + 1] = __uint_as_float(h11);
            g_klo[iA]     = __uint_as_float(f2tf32(v00 - __uint_as_float(h00)));
            g_klo[iA + 1] = __uint_as_float(f2tf32(v01 - __uint_as_float(h01)));
            g_klo[iB]     = __uint_as_float(f2tf32(v10 - __uint_as_float(h10)));
            g_klo[iB + 1] = __uint_as_float(f2tf32(v11 - __uint_as_float(h11)));
        } else {
            int hh = n >> 7, c = n & 127;
            int iA = (hh * N_TOK + mA) * DV + c;
            int iB = (hh * N_TOK + mB) * DV + c;
            g_vt[iA]     = __uint_as_float(f2tf32(v00));
            g_vt[iA + 1] = __uint_as_float(f2tf32(v01));
            g_vt[iB]     = __uint_as_float(f2tf32(v10));
            g_vt[iB + 1] = __uint_as_float(f2tf32(v11));
        }
    }
}

// ======================================================================
// Output projection, split-K=4. grid (18, 6, 4), 256 threads.
// Each z-slice accumulates K in [z*256, (z+1)*256) and writes a partial.
// ======================================================================
__global__ __launch_bounds__(256)
void proj_mma(void) {
    extern __shared__ float smp[];
    const uint32_t smb = (uint32_t)__cvta_generic_to_shared(smp);
    const int t = threadIdx.x, w = t >> 5, lane = t & 31;
    const int gid = lane >> 2, tig = lane & 3;
    const int m0 = blockIdx.x * 128;
    const int n0 = blockIdx.y * 64;
    const int z  = blockIdx.z;

    float acc[8][4];
    #pragma unroll
    for (int nt = 0; nt < 8; nt++)
        #pragma unroll
        for (int i = 0; i < 4; i++) acc[nt][i] = 0.0f;

    gemm3x_main<DH, DH / PROJ_SPLIT>(g_ohi, g_olo, g_pwhi, g_pwlo,
                                     m0, n0, z * (DH / PROJ_SPLIT), smp, smb, acc);

    float* pp = g_pp + (long)z * N_TOK * DIM;
    const int mA = m0 + w * 16 + gid;
    const int mB = mA + 8;
    #pragma unroll
    for (int nt = 0; nt < 8; nt++) {
        const int n = n0 + nt * 8 + 2 * tig;
        float2 r0, r1;
        r0.x = acc[nt][0]; r0.y = acc[nt][1];
        r1.x = acc[nt][2]; r1.y = acc[nt][3];
        *(float2*)&pp[mA * DIM + n] = r0;
        *(float2*)&pp[mB * DIM + n] = r1;
    }
}

// proj_reduce: out = sum of partials + bias (deterministic order)
#define PR_TOT (N_TOK * DIM)
__global__ void proj_reduce(const float* __restrict__ pbias, float* __restrict__ out) {
    int i = blockIdx.x * 256 + threadIdx.x;
    if (i >= PR_TOT) return;
    float s = g_pp[i] + g_pp[i + PR_TOT];
    s += g_pp[i + 2 * PR_TOT] + g_pp[i + 3 * PR_TOT];
    out[i] = s + pbias[i % DIM];
}

// ======================================================================
// Flash attention, tf32 mma, cp.async double-buffered pipeline.
// Grid (18, 8), 256 threads (8 warps), BM=128 q rows, key tiles of 64.
// (R5 structure; adds packed key-coordinate table to kill div/mod ALU.)
// ======================================================================
#define BM 128
#define BN 64
#define NTILE (N_TOK / BN)
#define KSTR 36
#define VSTR 136
#define PSTR 68

#define OF_K(b)  ((b) * 4608)            // Khi at +0, Klo at +2304
#define OF_V(b)  (9216 + (b) * 8704)
#define OF_PS    26624
#define OF_BIA   35328
#define OF_KCO   37632                    // 2304 packed int (ky<<8|kx)
#define SM_TOT   39936                    // floats = 159744 bytes

__global__ __launch_bounds__(256, 1)
void attn_mma(const float* __restrict__ Qg,
              const float* __restrict__ Khig,
              const float* __restrict__ Klog,
              const float* __restrict__ Vg,
              const float* __restrict__ biases) {   // [8, 2304]
    extern __shared__ float sm[];
    const uint32_t smb = (uint32_t)__cvta_generic_to_shared(sm);
    float* Ps = sm + OF_PS;
    float* bias_sm = sm + OF_BIA;
    int*   kco = (int*)(sm + OF_KCO);

    const int t    = threadIdx.x;
    const int w    = t >> 5;
    const int lane = t & 31;
    const int gid  = lane >> 2;
    const int tig  = lane & 3;
    const int qb   = blockIdx.x * BM;
    const int h    = blockIdx.y;

    const float* Kh_base = Khig + (h * N_TOK) * KD;
    const float* Kl_base = Klog + (h * N_TOK) * KD;
    const float* V_base  = Vg   + (h * N_TOK) * DV;

    const int row0 = qb + 16 * w + gid;
    const int row1 = row0 + 8;
    const int qy0 = row0 / RES, qx0 = row0 % RES;
    const int qy1 = row1 / RES, qx1 = row1 % RES;

    // per-head bias table + packed key coordinates
    for (int i = t; i < N_TOK; i += 256) {
        bias_sm[i] = biases[h * N_TOK + i];
        kco[i] = ((i / RES) << 8) | (i % RES);
    }

    // loop-invariant Q fragments, direct from head-major global
    uint32_t qhi[4][4], qlo[4][4];
    {
        const float* Qrow0 = Qg + (h * N_TOK + row0) * KD;
        const float* Qrow1 = Qg + (h * N_TOK + row1) * KD;
        #pragma unroll
        for (int ks = 0; ks < 4; ks++) {
            float x0 = Qrow0[ks * 8 + tig];
            float x1 = Qrow1[ks * 8 + tig];
            float x2 = Qrow0[ks * 8 + tig + 4];
            float x3 = Qrow1[ks * 8 + tig + 4];
            uint32_t h0 = f2tf32(x0), h1 = f2tf32(x1), h2 = f2tf32(x2), h3 = f2tf32(x3);
            qhi[ks][0] = h0; qhi[ks][1] = h1; qhi[ks][2] = h2; qhi[ks][3] = h3;
            qlo[ks][0] = f2tf32(x0 - __uint_as_float(h0));
            qlo[ks][1] = f2tf32(x1 - __uint_as_float(h1));
            qlo[ks][2] = f2tf32(x2 - __uint_as_float(h2));
            qlo[ks][3] = f2tf32(x3 - __uint_as_float(h3));
        }
    }

    // ---- async tile loader ----
    auto issue_tile = [&](int kt, int b) {
        const int kb = kt * BN;
        const float* kh = Kh_base + kb * KD;
        const float* kl = Kl_base + kb * KD;
        const float* vv = V_base + kb * DV;
        #pragma unroll
        for (int i = 0; i < 2; i++) {
            int c = t + i * 256;            // 0..511
            int r = c >> 3, f4 = c & 7;
            cp_async16(smb + (OF_K(b) + r * KSTR + f4 * 4) * 4, kh + r * KD + f4 * 4);
            cp_async16(smb + (OF_K(b) + 2304 + r * KSTR + f4 * 4) * 4, kl + r * KD + f4 * 4);
        }
        #pragma unroll
        for (int i = 0; i < 8; i++) {
            int c = t + i * 256;            // 0..2047
            int r = c >> 5, f4 = c & 31;
            cp_async16(smb + (OF_V(b) + r * VSTR + f4 * 4) * 4, vv + r * DV + f4 * 4);
        }
    };

    float m_r0 = -1e30f, m_r1 = -1e30f;
    float l_r0 = 0.0f,   l_r1 = 0.0f;
    float o[16][4];
    #pragma unroll
    for (int nt = 0; nt < 16; nt++)
        #pragma unroll
        for (int i = 0; i < 4; i++) o[nt][i] = 0.0f;

    issue_tile(0, 0);
    cp_commit();

    for (int kt = 0; kt < NTILE; kt++) {
        const int b  = kt & 1;
        const int kb = kt * BN;
        float* Khi = sm + OF_K(b);
        float* Klo = Khi + 2304;
        float* Vs  = sm + OF_V(b);

        if (kt + 1 < NTILE) {
            issue_tile(kt + 1, b ^ 1);
            cp_commit();
            asm volatile("cp.async.wait_group 1;");
        } else {
            asm volatile("cp.async.wait_group 0;");
        }
        __syncthreads();

        // ---- S = Q K^T (3x tf32) ----
        float sfr[8][4];
        #pragma unroll
        for (int nt = 0; nt < 8; nt++)
            #pragma unroll
            for (int i = 0; i < 4; i++) sfr[nt][i] = 0.0f;

        #pragma unroll
        for (int ks = 0; ks < 4; ks++) {
            #pragma unroll
            for (int nt = 0; nt < 8; nt++) {
                int nrow = nt * 8 + gid;
                uint32_t bh0 = __float_as_uint(Khi[nrow * KSTR + ks * 8 + tig]);
                uint32_t bh1 = __float_as_uint(Khi[nrow * KSTR + ks * 8 + tig + 4]);
                uint32_t bl0 = __float_as_uint(Klo[nrow * KSTR + ks * 8 + tig]);
                uint32_t bl1 = __float_as_uint(Klo[nrow * KSTR + ks * 8 + tig + 4]);
                mma_tf32(sfr[nt][0], sfr[nt][1], sfr[nt][2], sfr[nt][3],
                         qhi[ks][0], qhi[ks][1], qhi[ks][2], qhi[ks][3], bh0, bh1);
                mma_tf32(sfr[nt][0], sfr[nt][1], sfr[nt][2], sfr[nt][3],
                         qlo[ks][0], qlo[ks][1], qlo[ks][2], qlo[ks][3], bh0, bh1);
                mma_tf32(sfr[nt][0], sfr[nt][1], sfr[nt][2], sfr[nt][3],
                         qhi[ks][0], qhi[ks][1], qhi[ks][2], qhi[ks][3], bl0, bl1);
            }
        }

        // ---- scale + bias (table-driven), row max ----
        float mx0 = -1e30f, mx1 = -1e30f;
        #pragma unroll
        for (int nt = 0; nt < 8; nt++) {
            int cbase = kb + nt * 8 + 2 * tig;
            int pc0 = kco[cbase], pc1 = kco[cbase + 1];
            int ky0 = pc0 >> 8, kx0 = pc0 & 255;
            int ky1 = pc1 >> 8, kx1 = pc1 & 255;
            float b00 = bias_sm[abs(qy0 - ky0) * RES + abs(qx0 - kx0)];
            float b01 = bias_sm[abs(qy0 - ky1) * RES + abs(qx0 - kx1)];
            float b10 = bias_sm[abs(qy1 - ky0) * RES + abs(qx1 - kx0)];
            float b11 = bias_sm[abs(qy1 - ky1) * RES + abs(qx1 - kx1)];
            sfr[nt][0] = sfr[nt][0] * QSCALE + b00;
            sfr[nt][1] = sfr[nt][1] * QSCALE + b01;
            sfr[nt][2] = sfr[nt][2] * QSCALE + b10;
            sfr[nt][3] = sfr[nt][3] * QSCALE + b11;
            mx0 = fmaxf(mx0, fmaxf(sfr[nt][0], sfr[nt][1]));
            mx1 = fmaxf(mx1, fmaxf(sfr[nt][2], sfr[nt][3]));
        }
        mx0 = fmaxf(mx0, __shfl_xor_sync(0xffffffffu, mx0, 1));
        mx0 = fmaxf(mx0, __shfl_xor_sync(0xffffffffu, mx0, 2));
        mx1 = fmaxf(mx1, __shfl_xor_sync(0xffffffffu, mx1, 1));
        mx1 = fmaxf(mx1, __shfl_xor_sync(0xffffffffu, mx1, 2));

        float mn0 = fmaxf(m_r0, mx0);
        float mn1 = fmaxf(m_r1, mx1);
        float al0 = __expf(m_r0 - mn0);
        float al1 = __expf(m_r1 - mn1);
        m_r0 = mn0; m_r1 = mn1;

        // ---- P = exp(S - m), tf32 into smem, row sums ----
        float sum0 = 0.0f, sum1 = 0.0f;
        const int prow0 = (16 * w + gid) * PSTR;
        const int prow1 = (16 * w + gid + 8) * PSTR;
        #pragma unroll
        for (int nt = 0; nt < 8; nt++) {
            float p0 = __expf(sfr[nt][0] - mn0);
            float p1 = __expf(sfr[nt][1] - mn0);
            float p2 = __expf(sfr[nt][2] - mn1);
            float p3 = __expf(sfr[nt][3] - mn1);
            sum0 += p0 + p1;
            sum1 += p2 + p3;
            float2 w0, w1;
            w0.x = __uint_as_float(f2tf32(p0));
            w0.y = __uint_as_float(f2tf32(p1));
            w1.x = __uint_as_float(f2tf32(p2));
            w1.y = __uint_as_float(f2tf32(p3));
            *(float2*)&Ps[prow0 + nt * 8 + 2 * tig] = w0;
            *(float2*)&Ps[prow1 + nt * 8 + 2 * tig] = w1;
        }
        sum0 += __shfl_xor_sync(0xffffffffu, sum0, 1);
        sum0 += __shfl_xor_sync(0xffffffffu, sum0, 2);
        sum1 += __shfl_xor_sync(0xffffffffu, sum1, 1);
        sum1 += __shfl_xor_sync(0xffffffffu, sum1, 2);
        l_r0 = l_r0 * al0 + sum0;
        l_r1 = l_r1 * al1 + sum1;

        // rescale O accumulators
        #pragma unroll
        for (int nt = 0; nt < 16; nt++) {
            o[nt][0] *= al0; o[nt][1] *= al0;
            o[nt][2] *= al1; o[nt][3] *= al1;
        }
        __syncthreads();   // Ps visible to all warps

        // ---- O += P * V (1x tf32) ----
        #pragma unroll
        for (int ks = 0; ks < 8; ks++) {
            uint32_t pa0 = __float_as_uint(Ps[prow0 + ks * 8 + tig]);
            uint32_t pa1 = __float_as_uint(Ps[prow1 + ks * 8 + tig]);
            uint32_t pa2 = __float_as_uint(Ps[prow0 + ks * 8 + tig + 4]);
            uint32_t pa3 = __float_as_uint(Ps[prow1 + ks * 8 + tig + 4]);
            #pragma unroll
            for (int nt = 0; nt < 16; nt++) {
                uint32_t vb0 = __float_as_uint(Vs[(ks * 8 + tig) * VSTR + nt * 8 + gid]);
                uint32_t vb1 = __float_as_uint(Vs[(ks * 8 + tig + 4) * VSTR + nt * 8 + gid]);
                mma_tf32(o[nt][0], o[nt][1], o[nt][2], o[nt][3],
                         pa0, pa1, pa2, pa3, vb0, vb1);
            }
        }
        __syncthreads();   // done with this buffer + Ps before refill
    }

    // ---- epilogue: normalize, split hi/lo for proj ----
    float inv0 = 1.0f / l_r0;
    float inv1 = 1.0f / l_r1;
    #pragma unroll
    for (int nt = 0; nt < 16; nt++) {
        float v00 = o[nt][0] * inv0, v01 = o[nt][1] * inv0;
        float v10 = o[nt][2] * inv1, v11 = o[nt][3] * inv1;
        uint32_t h00 = f2tf32(v00), h01 = f2tf32(v01);
        uint32_t h10 = f2tf32(v10), h11 = f2tf32(v11);
        float2 hi0, hi1, lo0, lo1;
        hi0.x = __uint_as_float(h00); hi0.y = __uint_as_float(h01);
        hi1.x = __uint_as_float(h10); hi1.y = __uint_as_float(h11);
        lo0.x = __uint_as_float(f2tf32(v00 - __uint_as_float(h00)));
        lo0.y = __uint_as_float(f2tf32(v01 - __uint_as_float(h01)));
        lo1.x = __uint_as_float(f2tf32(v10 - __uint_as_float(h10)));
        lo1.y = __uint_as_float(f2tf32(v11 - __uint_as_float(h11)));
        long iA = (long)row0 * DH + h * DV + nt * 8 + 2 * tig;
        long iB = (long)row1 * DH + h * DV + nt * 8 + 2 * tig;
        *(float2*)&g_ohi[iA] = hi0;
        *(float2*)&g_ohi[iB] = hi1;
        *(float2*)&g_olo[iA] = lo0;
        *(float2*)&g_olo[iB] = lo1;
    }
}

// ======================================================================
extern "C" void kernel_launch(void* const* d_in, const int* in_sizes, int n_in,
                              void* d_out, int out_size) {
    const float* x       = (const float*)d_in[0];
    const float* q_w     = (const float*)d_in[1];
    const float* q_b     = (const float*)d_in[2];
    const float* k_w     = (const float*)d_in[3];
    const float* k_b     = (const float*)d_in[4];
    const float* v_w     = (const float*)d_in[5];
    const float* v_b     = (const float*)d_in[6];
    const float* proj_w  = (const float*)d_in[7];
    const float* proj_b  = (const float*)d_in[8];
    const float* abias   = (const float*)d_in[9];
    float* out           = (float*)d_out;

    float *pq, *pkh, *pkl, *pv;
    cudaGetSymbolAddress((void**)&pq,  g_qh);
    cudaGetSymbolAddress((void**)&pkh, g_khi);
    cudaGetSymbolAddress((void**)&pkl, g_klo);
    cudaGetSymbolAddress((void**)&pv,  g_vt);

    // 1. hi/lo split of x + weights
    split_prep<<<PREP_TOT / 256, 256>>>(x, q_w, k_w, v_w, proj_w);

    // 2. fused QKV projection (3xTF32 mma)
    const int gemm_smem = GEMM_SMEM_FLOATS * (int)sizeof(float);
    cudaFuncSetAttribute(qkv_mma, cudaFuncAttributeMaxDynamicSharedMemorySize, gemm_smem);
    qkv_mma<<<dim3(N_TOK / 128, 24), 256, gemm_smem>>>(q_b, k_b, v_b);

    // 3. fused attention (tf32 mma flash, cp.async pipelined)
    const int attn_smem = SM_TOT * (int)sizeof(float);
    cudaFuncSetAttribute(attn_mma, cudaFuncAttributeMaxDynamicSharedMemorySize, attn_smem);
    attn_mma<<<dim3(N_TOK / BM, NHEAD), 256, attn_smem>>>(pq, pkh, pkl, pv, abias);

    // 4. output projection, split-K=4 + deterministic reduce -> d_out
    cudaFuncSetAttribute(proj_mma, cudaFuncAttributeMaxDynamicSharedMemorySize, gemm_smem);
    proj_mma<<<dim3(N_TOK / 128, DIM / 64, PROJ_SPLIT), 256, gemm_smem>>>();
    proj_reduce<<<(PR_TOT + 255) / 256, 256>>>(proj_b, out);
}